// round 7
// baseline (speedup 1.0000x reference)
#include <cuda_runtime.h>
#include <cstdint>

#define BB 4
#define CC 192
#define NN 8192
#define KK 16
#define COUT 192
#define TWOC 384

typedef unsigned long long ull;

__device__ float g_xt [(size_t)BB * NN * CC];    // x as [B, N, C]
__device__ float g_rel[(size_t)BB * CC * NN];    // rel as [B, C, N]
__device__ float g_part[(size_t)BB * COUT * NN]; // x-half partial sums

// ---------------------------------------------------------------------------
// Kernel 1: transpose 2 batches: x [C, N] -> g_xt [N, C], b = b0 + blockIdx.z
// ---------------------------------------------------------------------------
__global__ void transpose_kernel(const float* __restrict__ x, int b0) {
    __shared__ float tile[32][33];
    int b  = b0 + blockIdx.z;
    int n0 = blockIdx.x * 32;
    int c0 = blockIdx.y * 32;
    int tx = threadIdx.x, ty = threadIdx.y;
    const float* in  = x    + (size_t)b * CC * NN;
    float*      outp = g_xt + (size_t)b * NN * CC;
#pragma unroll
    for (int i = 0; i < 32; i += 8)
        tile[ty + i][tx] = in[(size_t)(c0 + ty + i) * NN + n0 + tx];
    __syncthreads();
#pragma unroll
    for (int i = 0; i < 32; i += 8)
        outp[(size_t)(n0 + ty + i) * CC + c0 + tx] = tile[tx][ty + i];
}

// ---------------------------------------------------------------------------
// Kernel 2: gather + max-relative for 2 batches -> g_rel [C, N]
// 512 blocks/launch; 32 nodes/block; warp does 2 nodes concurrently (MLP).
// ---------------------------------------------------------------------------
#define GA_NODES 32
#define SR_S 33

__global__ __launch_bounds__(256)
void gather_kernel(const int* __restrict__ edge, int b0) {
    __shared__ float srel[CC * SR_S];
    __shared__ int   sj[GA_NODES * KK];
    __shared__ int   si[GA_NODES * KK];

    const int tid = threadIdx.x;
    const int bid = blockIdx.x;
    const int b   = b0 + (bid >> 8);
    const int n0  = (bid & 255) * GA_NODES;

    const int* ej = edge + ((size_t)b * NN + n0) * KK;
    const int* ei = edge + ((size_t)(BB + b) * NN + n0) * KK;
    for (int t = tid; t < GA_NODES * KK; t += 256) {
        sj[t] = ej[t];
        si[t] = ei[t];
    }
    __syncthreads();

    const float* bx = g_xt + (size_t)b * NN * CC;
    const int wid  = tid >> 5;
    const int lane = tid & 31;
    const int cb   = lane * 2;

#pragma unroll
    for (int t = 0; t < 2; t++) {
        const int nA = wid + t * 16;
        const int nB = nA + 8;
        float2 a0 = make_float2(-3.0e38f, -3.0e38f), a1 = a0, a2 = a0;
        float2 b0v = a0, b1 = a0, b2 = a0;
        const int* sjA = sj + nA * KK; const int* siA = si + nA * KK;
        const int* sjB = sj + nB * KK; const int* siB = si + nB * KK;
#pragma unroll 2
        for (int k = 0; k < KK; k++) {
            const float* pjA = bx + (size_t)sjA[k] * CC + cb;
            const float* piA = bx + (size_t)siA[k] * CC + cb;
            const float* pjB = bx + (size_t)sjB[k] * CC + cb;
            const float* piB = bx + (size_t)siB[k] * CC + cb;
            float2 ja0 = *(const float2*)(pjA);       float2 ia0 = *(const float2*)(piA);
            float2 ja1 = *(const float2*)(pjA + 64);  float2 ia1 = *(const float2*)(piA + 64);
            float2 ja2 = *(const float2*)(pjA + 128); float2 ia2 = *(const float2*)(piA + 128);
            float2 jb0 = *(const float2*)(pjB);       float2 ib0 = *(const float2*)(piB);
            float2 jb1 = *(const float2*)(pjB + 64);  float2 ib1 = *(const float2*)(piB + 64);
            float2 jb2 = *(const float2*)(pjB + 128); float2 ib2 = *(const float2*)(piB + 128);
            a0.x = fmaxf(a0.x, ja0.x - ia0.x); a0.y = fmaxf(a0.y, ja0.y - ia0.y);
            a1.x = fmaxf(a1.x, ja1.x - ia1.x); a1.y = fmaxf(a1.y, ja1.y - ia1.y);
            a2.x = fmaxf(a2.x, ja2.x - ia2.x); a2.y = fmaxf(a2.y, ja2.y - ia2.y);
            b0v.x = fmaxf(b0v.x, jb0.x - ib0.x); b0v.y = fmaxf(b0v.y, jb0.y - ib0.y);
            b1.x = fmaxf(b1.x, jb1.x - ib1.x); b1.y = fmaxf(b1.y, jb1.y - ib1.y);
            b2.x = fmaxf(b2.x, jb2.x - ib2.x); b2.y = fmaxf(b2.y, jb2.y - ib2.y);
        }
        srel[(cb)       * SR_S + nA] = a0.x; srel[(cb + 1)   * SR_S + nA] = a0.y;
        srel[(cb + 64)  * SR_S + nA] = a1.x; srel[(cb + 65)  * SR_S + nA] = a1.y;
        srel[(cb + 128) * SR_S + nA] = a2.x; srel[(cb + 129) * SR_S + nA] = a2.y;
        srel[(cb)       * SR_S + nB] = b0v.x; srel[(cb + 1)   * SR_S + nB] = b0v.y;
        srel[(cb + 64)  * SR_S + nB] = b1.x;  srel[(cb + 65)  * SR_S + nB] = b1.y;
        srel[(cb + 128) * SR_S + nB] = b2.x;  srel[(cb + 129) * SR_S + nB] = b2.y;
    }
    __syncthreads();

    float* ro = g_rel + (size_t)b * CC * NN + n0;
    for (int t = tid; t < CC * GA_NODES; t += 256) {
        int c = t >> 5, n = t & 31;
        ro[(size_t)c * NN + n] = srel[c * SR_S + n];
    }
}

// ---------------------------------------------------------------------------
// GEMM halves: 512 threads, 64-node tile, 3 outputs x 8 nodes per thread.
// ---------------------------------------------------------------------------
#define GT 512
#define GN 64
#define KC 32
#define NCHH (CC / KC)       // 6
#define WPD 33

#define YCH_BYTES (KC * GN * 4)
#define WSD_OFF   YCH_BYTES
#define GEMM_SMEM (WSD_OFF + COUT * WPD * 8)   // 58880

__device__ __forceinline__ void gemm_half(const float* __restrict__ ysrc,
                                          const float* __restrict__ W, int wc0,
                                          int tid, int oi, int ni,
                                          float* ych, float2* wsd, ull acc[3][4]) {
    ull* wsq = (ull*)wsd;
    const ull* wp = wsq + oi * 3 * WPD;

    float4 pf = *(const float4*)(ysrc + (size_t)(tid >> 4) * NN + (tid & 15) * 4);

    for (int ch = 0; ch < NCHH; ch++) {
        ((float4*)ych)[tid] = pf;
        const float* wsrc = W + wc0 + ch * KC;
        for (int t = tid; t < COUT * KC; t += GT) {
            int o = t >> 5, k = t & 31;
            float v = wsrc[(size_t)o * TWOC + k];
            wsd[o * WPD + k] = make_float2(v, v);
        }
        __syncthreads();

        if (ch + 1 < NCHH) {
            const float* s = ysrc + (size_t)(ch + 1) * KC * NN;
            pf = *(const float4*)(s + (size_t)(tid >> 4) * NN + (tid & 15) * 4);
        }

#pragma unroll 8
        for (int kk = 0; kk < KC; kk++) {
            longlong2 qa = *(const longlong2*)(ych + kk * GN + ni * 4);
            longlong2 qb = *(const longlong2*)(ych + kk * GN + 32 + ni * 4);
            ull y2[4] = { (ull)qa.x, (ull)qa.y, (ull)qb.x, (ull)qb.y };
#pragma unroll
            for (int m = 0; m < 3; m++) {
                ull w = wp[m * WPD + kk];
#pragma unroll
                for (int p = 0; p < 4; p++)
                    asm("fma.rn.f32x2 %0, %1, %2, %3;"
                        : "=l"(acc[m][p]) : "l"(w), "l"(y2[p]), "l"(acc[m][p]));
            }
        }
        __syncthreads();
    }
}

// x-half GEMM (all 4 batches, gather-independent): raw partials to g_part.
__global__ __launch_bounds__(GT, 2)
void gemm_x_kernel(const float* __restrict__ x, const float* __restrict__ W) {
    extern __shared__ char smem[];
    float*  ych = (float*)smem;
    float2* wsd = (float2*)(smem + WSD_OFF);

    const int tid = threadIdx.x;
    const int bid = blockIdx.x;
    const int b   = bid >> 7;
    const int n0  = (bid & 127) * GN;
    const int oi  = tid >> 3;
    const int ni  = tid & 7;

    ull acc[3][4];
#pragma unroll
    for (int m = 0; m < 3; m++)
#pragma unroll
        for (int p = 0; p < 4; p++) acc[m][p] = 0ULL;

    gemm_half(x + (size_t)b * CC * NN + n0, W, 0, tid, oi, ni, ych, wsd, acc);

    float* pb = g_part + (size_t)b * COUT * NN + n0 + ni * 4;
#pragma unroll
    for (int m = 0; m < 3; m++) {
        float* op = pb + (size_t)(oi * 3 + m) * NN;
        float4 v0, v1; float a, c;
        asm("mov.b64 {%0, %1}, %2;" : "=f"(a), "=f"(c) : "l"(acc[m][0])); v0.x = a; v0.y = c;
        asm("mov.b64 {%0, %1}, %2;" : "=f"(a), "=f"(c) : "l"(acc[m][1])); v0.z = a; v0.w = c;
        asm("mov.b64 {%0, %1}, %2;" : "=f"(a), "=f"(c) : "l"(acc[m][2])); v1.x = a; v1.y = c;
        asm("mov.b64 {%0, %1}, %2;" : "=f"(a), "=f"(c) : "l"(acc[m][3])); v1.z = a; v1.w = c;
        *(float4*)(op)      = v0;
        *(float4*)(op + 32) = v1;
    }
}

// rel-half GEMM for 2 batches: adds partial + bias, relu, writes out.
__global__ __launch_bounds__(GT, 2)
void gemm_rel_kernel(int b0, const float* __restrict__ W,
                     const float* __restrict__ bias, float* __restrict__ out) {
    extern __shared__ char smem[];
    float*  ych = (float*)smem;
    float2* wsd = (float2*)(smem + WSD_OFF);

    const int tid = threadIdx.x;
    const int bid = blockIdx.x;
    const int b   = b0 + (bid >> 7);
    const int n0  = (bid & 127) * GN;
    const int oi  = tid >> 3;
    const int ni  = tid & 7;

    float bv[3];
#pragma unroll
    for (int m = 0; m < 3; m++) bv[m] = bias[oi * 3 + m];

    ull acc[3][4];
#pragma unroll
    for (int m = 0; m < 3; m++)
#pragma unroll
        for (int p = 0; p < 4; p++) acc[m][p] = 0ULL;

    gemm_half(g_rel + (size_t)b * CC * NN + n0, W, CC, tid, oi, ni, ych, wsd, acc);

    const float* pb = g_part + (size_t)b * COUT * NN + n0 + ni * 4;
    float*       ob = out    + (size_t)b * COUT * NN + n0 + ni * 4;
#pragma unroll
    for (int m = 0; m < 3; m++) {
        const float* pp = pb + (size_t)(oi * 3 + m) * NN;
        float4 p0 = *(const float4*)(pp);
        float4 p1 = *(const float4*)(pp + 32);
        float4 v0, v1; float a, c;
        asm("mov.b64 {%0, %1}, %2;" : "=f"(a), "=f"(c) : "l"(acc[m][0]));
        v0.x = fmaxf(p0.x + a + bv[m], 0.0f); v0.y = fmaxf(p0.y + c + bv[m], 0.0f);
        asm("mov.b64 {%0, %1}, %2;" : "=f"(a), "=f"(c) : "l"(acc[m][1]));
        v0.z = fmaxf(p0.z + a + bv[m], 0.0f); v0.w = fmaxf(p0.w + c + bv[m], 0.0f);
        asm("mov.b64 {%0, %1}, %2;" : "=f"(a), "=f"(c) : "l"(acc[m][2]));
        v1.x = fmaxf(p1.x + a + bv[m], 0.0f); v1.y = fmaxf(p1.y + c + bv[m], 0.0f);
        asm("mov.b64 {%0, %1}, %2;" : "=f"(a), "=f"(c) : "l"(acc[m][3]));
        v1.z = fmaxf(p1.z + a + bv[m], 0.0f); v1.w = fmaxf(p1.w + c + bv[m], 0.0f);
        float* op = ob + (size_t)(oi * 3 + m) * NN;
        *(float4*)(op)      = v0;
        *(float4*)(op + 32) = v1;
    }
}

// ---------------------------------------------------------------------------
// Launch: half-batch pipeline.
//   sB: gemm_x (all batches) -> eX
//   sA: transpose(b0,b1); gather(b0,b1) -> eG0; transpose(b2,b3); gather(b2,b3) -> eG1
//   s0: wait eX; wait eG0: gemm_rel(b0,b1); wait eG1: gemm_rel(b2,b3)
// ---------------------------------------------------------------------------
extern "C" void kernel_launch(void* const* d_in, const int* in_sizes, int n_in,
                              void* d_out, int out_size) {
    const float* x    = (const float*)d_in[0];
    const int*   edge = (const int*)d_in[2];
    const float* W    = (const float*)d_in[3];
    const float* bias = (const float*)d_in[4];
    float*       out  = (float*)d_out;

    static cudaStream_t sA = nullptr, sB = nullptr;
    static cudaEvent_t  eFork = nullptr, eX = nullptr, eG0 = nullptr, eG1 = nullptr;
    if (sA == nullptr) {
        cudaStreamCreateWithFlags(&sA, cudaStreamNonBlocking);
        cudaStreamCreateWithFlags(&sB, cudaStreamNonBlocking);
        cudaEventCreateWithFlags(&eFork, cudaEventDisableTiming);
        cudaEventCreateWithFlags(&eX, cudaEventDisableTiming);
        cudaEventCreateWithFlags(&eG0, cudaEventDisableTiming);
        cudaEventCreateWithFlags(&eG1, cudaEventDisableTiming);
        cudaFuncSetAttribute(gemm_x_kernel,
                             cudaFuncAttributeMaxDynamicSharedMemorySize, GEMM_SMEM);
        cudaFuncSetAttribute(gemm_rel_kernel,
                             cudaFuncAttributeMaxDynamicSharedMemorySize, GEMM_SMEM);
    }

    cudaEventRecord(eFork, 0);
    cudaStreamWaitEvent(sA, eFork, 0);
    cudaStreamWaitEvent(sB, eFork, 0);

    // sB: gather-independent x-half GEMM over all batches
    gemm_x_kernel<<<BB * (NN / GN), GT, GEMM_SMEM, sB>>>(x, W);
    cudaEventRecord(eX, sB);

    // sA: half 0 (b0,b1), then half 1 (b2,b3)
    transpose_kernel<<<dim3(NN / 32, CC / 32, 2), dim3(32, 8), 0, sA>>>(x, 0);
    gather_kernel<<<2 * (NN / GA_NODES), 256, 0, sA>>>(edge, 0);
    cudaEventRecord(eG0, sA);
    transpose_kernel<<<dim3(NN / 32, CC / 32, 2), dim3(32, 8), 0, sA>>>(x, 2);
    gather_kernel<<<2 * (NN / GA_NODES), 256, 0, sA>>>(edge, 2);
    cudaEventRecord(eG1, sA);

    // s0: rel halves as their gathers land
    cudaStreamWaitEvent(0, eX, 0);
    cudaStreamWaitEvent(0, eG0, 0);
    gemm_rel_kernel<<<2 * (NN / GN), GT, GEMM_SMEM>>>(0, W, bias, out);
    cudaStreamWaitEvent(0, eG1, 0);
    gemm_rel_kernel<<<2 * (NN / GN), GT, GEMM_SMEM>>>(2, W, bias, out);
}

// round 9
// speedup vs baseline: 1.8961x; 1.8961x over previous
#include <cuda_runtime.h>
#include <cstdint>

#define BB 4
#define CC 192
#define NN 8192
#define KK 16
#define COUT 192
#define TWOC 384

typedef unsigned long long ull;

__device__ float g_xt [(size_t)BB * NN * CC];    // x as [B, N, C]
__device__ float g_rel[(size_t)BB * CC * NN];    // rel as [B, C, N]
__device__ float g_part[(size_t)BB * COUT * NN]; // x-half partial sums

// ---------------------------------------------------------------------------
// Kernel 1: transpose 2 batches: x [C, N] -> g_xt [N, C], b = b0 + blockIdx.z
// ---------------------------------------------------------------------------
__global__ void transpose_kernel(const float* __restrict__ x, int b0) {
    __shared__ float tile[32][33];
    int b  = b0 + blockIdx.z;
    int n0 = blockIdx.x * 32;
    int c0 = blockIdx.y * 32;
    int tx = threadIdx.x, ty = threadIdx.y;
    const float* in  = x    + (size_t)b * CC * NN;
    float*      outp = g_xt + (size_t)b * NN * CC;
#pragma unroll
    for (int i = 0; i < 32; i += 8)
        tile[ty + i][tx] = in[(size_t)(c0 + ty + i) * NN + n0 + tx];
    __syncthreads();
#pragma unroll
    for (int i = 0; i < 32; i += 8)
        outp[(size_t)(n0 + ty + i) * CC + c0 + tx] = tile[tx][ty + i];
}

// ---------------------------------------------------------------------------
// Kernel 2: gather + max-relative for 2 batches (b0, b0+1) -> g_rel [C, N]
// 512 blocks/launch, 32 nodes/block, warp handles 2 nodes concurrently.
// ---------------------------------------------------------------------------
#define GA_NODES 32
#define SR_S 33

__global__ __launch_bounds__(256)
void gather_kernel(const int* __restrict__ edge, int b0) {
    __shared__ float srel[CC * SR_S];
    __shared__ int   sj[GA_NODES * KK];
    __shared__ int   si[GA_NODES * KK];

    const int tid = threadIdx.x;
    const int bid = blockIdx.x;
    const int b   = b0 + (bid >> 8);
    const int n0  = (bid & 255) * GA_NODES;

    const int* ej = edge + ((size_t)b * NN + n0) * KK;
    const int* ei = edge + ((size_t)(BB + b) * NN + n0) * KK;
    for (int t = tid; t < GA_NODES * KK; t += 256) {
        sj[t] = ej[t];
        si[t] = ei[t];
    }
    __syncthreads();

    const float* bx = g_xt + (size_t)b * NN * CC;
    const int wid  = tid >> 5;
    const int lane = tid & 31;
    const int cb   = lane * 2;

#pragma unroll
    for (int t = 0; t < 2; t++) {
        const int nA = wid + t * 16;
        const int nB = nA + 8;
        float2 a0 = make_float2(-3.0e38f, -3.0e38f), a1 = a0, a2 = a0;
        float2 b0v = a0, b1 = a0, b2 = a0;
        const int* sjA = sj + nA * KK; const int* siA = si + nA * KK;
        const int* sjB = sj + nB * KK; const int* siB = si + nB * KK;
#pragma unroll 2
        for (int k = 0; k < KK; k++) {
            const float* pjA = bx + (size_t)sjA[k] * CC + cb;
            const float* piA = bx + (size_t)siA[k] * CC + cb;
            const float* pjB = bx + (size_t)sjB[k] * CC + cb;
            const float* piB = bx + (size_t)siB[k] * CC + cb;
            float2 ja0 = *(const float2*)(pjA);       float2 ia0 = *(const float2*)(piA);
            float2 ja1 = *(const float2*)(pjA + 64);  float2 ia1 = *(const float2*)(piA + 64);
            float2 ja2 = *(const float2*)(pjA + 128); float2 ia2 = *(const float2*)(piA + 128);
            float2 jb0 = *(const float2*)(pjB);       float2 ib0 = *(const float2*)(piB);
            float2 jb1 = *(const float2*)(pjB + 64);  float2 ib1 = *(const float2*)(piB + 64);
            float2 jb2 = *(const float2*)(pjB + 128); float2 ib2 = *(const float2*)(piB + 128);
            a0.x = fmaxf(a0.x, ja0.x - ia0.x); a0.y = fmaxf(a0.y, ja0.y - ia0.y);
            a1.x = fmaxf(a1.x, ja1.x - ia1.x); a1.y = fmaxf(a1.y, ja1.y - ia1.y);
            a2.x = fmaxf(a2.x, ja2.x - ia2.x); a2.y = fmaxf(a2.y, ja2.y - ia2.y);
            b0v.x = fmaxf(b0v.x, jb0.x - ib0.x); b0v.y = fmaxf(b0v.y, jb0.y - ib0.y);
            b1.x = fmaxf(b1.x, jb1.x - ib1.x); b1.y = fmaxf(b1.y, jb1.y - ib1.y);
            b2.x = fmaxf(b2.x, jb2.x - ib2.x); b2.y = fmaxf(b2.y, jb2.y - ib2.y);
        }
        srel[(cb)       * SR_S + nA] = a0.x; srel[(cb + 1)   * SR_S + nA] = a0.y;
        srel[(cb + 64)  * SR_S + nA] = a1.x; srel[(cb + 65)  * SR_S + nA] = a1.y;
        srel[(cb + 128) * SR_S + nA] = a2.x; srel[(cb + 129) * SR_S + nA] = a2.y;
        srel[(cb)       * SR_S + nB] = b0v.x; srel[(cb + 1)   * SR_S + nB] = b0v.y;
        srel[(cb + 64)  * SR_S + nB] = b1.x;  srel[(cb + 65)  * SR_S + nB] = b1.y;
        srel[(cb + 128) * SR_S + nB] = b2.x;  srel[(cb + 129) * SR_S + nB] = b2.y;
    }
    __syncthreads();

    float* ro = g_rel + (size_t)b * CC * NN + n0;
    for (int t = tid; t < CC * GA_NODES; t += 256) {
        int c = t >> 5, n = t & 31;
        ro[(size_t)c * NN + n] = srel[c * SR_S + n];
    }
}

// ---------------------------------------------------------------------------
// GEMM (R4 proven mapping): 256 threads, 64-node tile, 6 outputs x 8 nodes,
// 128 regs, 2 CTA/SM. Register-prefetch double buffer; FFMA2 inner loop.
// ---------------------------------------------------------------------------
#define GN 64
#define KC 32
#define NCHH (CC / KC)       // 6
#define WPD 33

#define YCH_BYTES (KC * GN * 4)
#define WSD_OFF   YCH_BYTES
#define GEMM_SMEM (WSD_OFF + COUT * WPD * 8)   // 58880

__device__ __forceinline__ void gemm_half(const float* __restrict__ ysrc,
                                          const float* __restrict__ W, int wc0,
                                          int tid, int oi, int ni,
                                          float* ych, float2* wsd, ull acc[6][4]) {
    ull* wsq = (ull*)wsd;
    const ull* wp = wsq + oi * 6 * WPD;

    float4 pf0, pf1;
    {
        int f0 = tid * 2, f1 = tid * 2 + 1;
        pf0 = *(const float4*)(ysrc + (size_t)(f0 >> 4) * NN + (f0 & 15) * 4);
        pf1 = *(const float4*)(ysrc + (size_t)(f1 >> 4) * NN + (f1 & 15) * 4);
    }

    for (int ch = 0; ch < NCHH; ch++) {
        ((float4*)ych)[tid * 2]     = pf0;
        ((float4*)ych)[tid * 2 + 1] = pf1;
        const float* wsrc = W + wc0 + ch * KC;
        for (int t = tid; t < COUT * KC; t += 256) {
            int o = t >> 5, k = t & 31;
            float v = wsrc[(size_t)o * TWOC + k];
            wsd[o * WPD + k] = make_float2(v, v);
        }
        __syncthreads();

        if (ch + 1 < NCHH) {
            const float* s = ysrc + (size_t)(ch + 1) * KC * NN;
            int f0 = tid * 2, f1 = tid * 2 + 1;
            pf0 = *(const float4*)(s + (size_t)(f0 >> 4) * NN + (f0 & 15) * 4);
            pf1 = *(const float4*)(s + (size_t)(f1 >> 4) * NN + (f1 & 15) * 4);
        }

#pragma unroll 8
        for (int kk = 0; kk < KC; kk++) {
            longlong2 qa = *(const longlong2*)(ych + kk * GN + ni * 4);
            longlong2 qb = *(const longlong2*)(ych + kk * GN + 32 + ni * 4);
            ull y2[4] = { (ull)qa.x, (ull)qa.y, (ull)qb.x, (ull)qb.y };
#pragma unroll
            for (int m = 0; m < 6; m++) {
                ull w = wp[m * WPD + kk];
#pragma unroll
                for (int p = 0; p < 4; p++)
                    asm("fma.rn.f32x2 %0, %1, %2, %3;"
                        : "=l"(acc[m][p]) : "l"(w), "l"(y2[p]), "l"(acc[m][p]));
            }
        }
        __syncthreads();
    }
}

// x-half GEMM (all 4 batches): raw partials to g_part.
__global__ __launch_bounds__(256, 2)
void gemm_x_kernel(const float* __restrict__ x, const float* __restrict__ W) {
    extern __shared__ char smem[];
    float*  ych = (float*)smem;
    float2* wsd = (float2*)(smem + WSD_OFF);

    const int tid = threadIdx.x;
    const int bid = blockIdx.x;
    const int b   = bid >> 7;
    const int n0  = (bid & 127) * GN;
    const int oi  = tid >> 3;
    const int ni  = tid & 7;

    ull acc[6][4];
#pragma unroll
    for (int m = 0; m < 6; m++)
#pragma unroll
        for (int p = 0; p < 4; p++) acc[m][p] = 0ULL;

    gemm_half(x + (size_t)b * CC * NN + n0, W, 0, tid, oi, ni, ych, wsd, acc);

    float* pb = g_part + (size_t)b * COUT * NN + n0 + ni * 4;
#pragma unroll
    for (int m = 0; m < 6; m++) {
        float* op = pb + (size_t)(oi * 6 + m) * NN;
        float4 v0, v1; float a, c;
        asm("mov.b64 {%0, %1}, %2;" : "=f"(a), "=f"(c) : "l"(acc[m][0])); v0.x = a; v0.y = c;
        asm("mov.b64 {%0, %1}, %2;" : "=f"(a), "=f"(c) : "l"(acc[m][1])); v0.z = a; v0.w = c;
        asm("mov.b64 {%0, %1}, %2;" : "=f"(a), "=f"(c) : "l"(acc[m][2])); v1.x = a; v1.y = c;
        asm("mov.b64 {%0, %1}, %2;" : "=f"(a), "=f"(c) : "l"(acc[m][3])); v1.z = a; v1.w = c;
        *(float4*)(op)      = v0;
        *(float4*)(op + 32) = v1;
    }
}

// rel-half GEMM for 2 batches (b0, b0+1): partial + bias, relu, store out.
__global__ __launch_bounds__(256, 2)
void gemm_rel_kernel(int b0, const float* __restrict__ W,
                     const float* __restrict__ bias, float* __restrict__ out) {
    extern __shared__ char smem[];
    float*  ych = (float*)smem;
    float2* wsd = (float2*)(smem + WSD_OFF);

    const int tid = threadIdx.x;
    const int bid = blockIdx.x;
    const int b   = b0 + (bid >> 7);
    const int n0  = (bid & 127) * GN;
    const int oi  = tid >> 3;
    const int ni  = tid & 7;

    float bv[6];
#pragma unroll
    for (int m = 0; m < 6; m++) bv[m] = bias[oi * 6 + m];

    ull acc[6][4];
#pragma unroll
    for (int m = 0; m < 6; m++)
#pragma unroll
        for (int p = 0; p < 4; p++) acc[m][p] = 0ULL;

    gemm_half(g_rel + (size_t)b * CC * NN + n0, W, CC, tid, oi, ni, ych, wsd, acc);

    const float* pb = g_part + (size_t)b * COUT * NN + n0 + ni * 4;
    float*       ob = out    + (size_t)b * COUT * NN + n0 + ni * 4;
#pragma unroll
    for (int m = 0; m < 6; m++) {
        const float* pp = pb + (size_t)(oi * 6 + m) * NN;
        float4 p0 = *(const float4*)(pp);
        float4 p1 = *(const float4*)(pp + 32);
        float4 v0, v1; float a, c;
        asm("mov.b64 {%0, %1}, %2;" : "=f"(a), "=f"(c) : "l"(acc[m][0]));
        v0.x = fmaxf(p0.x + a + bv[m], 0.0f); v0.y = fmaxf(p0.y + c + bv[m], 0.0f);
        asm("mov.b64 {%0, %1}, %2;" : "=f"(a), "=f"(c) : "l"(acc[m][1]));
        v0.z = fmaxf(p0.z + a + bv[m], 0.0f); v0.w = fmaxf(p0.w + c + bv[m], 0.0f);
        asm("mov.b64 {%0, %1}, %2;" : "=f"(a), "=f"(c) : "l"(acc[m][2]));
        v1.x = fmaxf(p1.x + a + bv[m], 0.0f); v1.y = fmaxf(p1.y + c + bv[m], 0.0f);
        asm("mov.b64 {%0, %1}, %2;" : "=f"(a), "=f"(c) : "l"(acc[m][3]));
        v1.z = fmaxf(p1.z + a + bv[m], 0.0f); v1.w = fmaxf(p1.w + c + bv[m], 0.0f);
        float* op = ob + (size_t)(oi * 6 + m) * NN;
        *(float4*)(op)      = v0;
        *(float4*)(op + 32) = v1;
    }
}

// ---------------------------------------------------------------------------
// Launch: half-batch pipeline with the proven 256-thread GEMM.
//   sB: gemm_x (all) -> eX
//   sC: transpose(b2,b3) -> eT23
//   sA: transpose(b0,b1); gather(b0,b1) -> eG0; [wait eT23] gather(b2,b3) -> eG1
//   s0: wait eX; wait eG0: gemm_rel(b0,b1); wait eG1: gemm_rel(b2,b3)
// ---------------------------------------------------------------------------
extern "C" void kernel_launch(void* const* d_in, const int* in_sizes, int n_in,
                              void* d_out, int out_size) {
    const float* x    = (const float*)d_in[0];
    const int*   edge = (const int*)d_in[2];
    const float* W    = (const float*)d_in[3];
    const float* bias = (const float*)d_in[4];
    float*       out  = (float*)d_out;

    static cudaStream_t sA = nullptr, sB = nullptr, sC = nullptr;
    static cudaEvent_t  eFork = nullptr, eX = nullptr, eT23 = nullptr,
                        eG0 = nullptr, eG1 = nullptr;
    if (sA == nullptr) {
        cudaStreamCreateWithFlags(&sA, cudaStreamNonBlocking);
        cudaStreamCreateWithFlags(&sB, cudaStreamNonBlocking);
        cudaStreamCreateWithFlags(&sC, cudaStreamNonBlocking);
        cudaEventCreateWithFlags(&eFork, cudaEventDisableTiming);
        cudaEventCreateWithFlags(&eX,   cudaEventDisableTiming);
        cudaEventCreateWithFlags(&eT23, cudaEventDisableTiming);
        cudaEventCreateWithFlags(&eG0,  cudaEventDisableTiming);
        cudaEventCreateWithFlags(&eG1,  cudaEventDisableTiming);
        cudaFuncSetAttribute(gemm_x_kernel,
                             cudaFuncAttributeMaxDynamicSharedMemorySize, GEMM_SMEM);
        cudaFuncSetAttribute(gemm_rel_kernel,
                             cudaFuncAttributeMaxDynamicSharedMemorySize, GEMM_SMEM);
    }

    cudaEventRecord(eFork, 0);
    cudaStreamWaitEvent(sA, eFork, 0);
    cudaStreamWaitEvent(sB, eFork, 0);
    cudaStreamWaitEvent(sC, eFork, 0);

    // sB: gather-independent x-half GEMM over all batches
    gemm_x_kernel<<<BB * (NN / GN), 256, GEMM_SMEM, sB>>>(x, W);
    cudaEventRecord(eX, sB);

    // sC: transpose of the second half, concurrent with the first half's work
    transpose_kernel<<<dim3(NN / 32, CC / 32, 2), dim3(32, 8), 0, sC>>>(x, 2);
    cudaEventRecord(eT23, sC);

    // sA: first-half transpose -> gather; then second-half gather
    transpose_kernel<<<dim3(NN / 32, CC / 32, 2), dim3(32, 8), 0, sA>>>(x, 0);
    gather_kernel<<<2 * (NN / GA_NODES), 256, 0, sA>>>(edge, 0);
    cudaEventRecord(eG0, sA);
    cudaStreamWaitEvent(sA, eT23, 0);
    gather_kernel<<<2 * (NN / GA_NODES), 256, 0, sA>>>(edge, 2);
    cudaEventRecord(eG1, sA);

    // s0: rel halves as their gathers land
    cudaStreamWaitEvent(0, eX, 0);
    cudaStreamWaitEvent(0, eG0, 0);
    gemm_rel_kernel<<<2 * (NN / GN), 256, GEMM_SMEM>>>(0, W, bias, out);
    cudaStreamWaitEvent(0, eG1, 0);
    gemm_rel_kernel<<<2 * (NN / GN), 256, GEMM_SMEM>>>(2, W, bias, out);
}

// round 12
// speedup vs baseline: 2.7802x; 1.4663x over previous
#include <cuda_runtime.h>
#include <cuda_bf16.h>
#include <cstdint>

#define BB 4
#define CC 192
#define NN 8192
#define KK 16
#define COUT 192
#define TWOC 384

// Scratch
__device__ float          g_xt [(size_t)BB * NN * CC];   // x as [B, N, C] fp32
__device__ __nv_bfloat16  g_xhi[(size_t)BB * NN * CC];   // bf16 hi of x, [B, N, C]
__device__ __nv_bfloat16  g_xlo[(size_t)BB * NN * CC];   // bf16 lo
__device__ __nv_bfloat16  g_rhi[(size_t)BB * NN * CC];   // bf16 hi of rel, [B, N, C]
__device__ __nv_bfloat16  g_rlo[(size_t)BB * NN * CC];
__device__ __nv_bfloat16  g_whi[COUT * TWOC];
__device__ __nv_bfloat16  g_wlo[COUT * TWOC];

__device__ __forceinline__ uint32_t smem_u32(const void* p) {
    uint32_t a;
    asm("{ .reg .u64 t; cvta.to.shared.u64 t, %1; cvt.u32.u64 %0, t; }"
        : "=r"(a) : "l"(p));
    return a;
}

// ---------------------------------------------------------------------------
// Kernel 1: transpose x [B,C,N] -> g_xt fp32 [B,N,C] + bf16 hi/lo
// ---------------------------------------------------------------------------
__global__ void transpose_kernel(const float* __restrict__ x) {
    __shared__ float tile[32][33];
    int b  = blockIdx.z;
    int n0 = blockIdx.x * 32;
    int c0 = blockIdx.y * 32;
    int tx = threadIdx.x, ty = threadIdx.y;
    const float* in = x + (size_t)b * CC * NN;
#pragma unroll
    for (int i = 0; i < 32; i += 8)
        tile[ty + i][tx] = in[(size_t)(c0 + ty + i) * NN + n0 + tx];
    __syncthreads();
    float*         oxt = g_xt  + (size_t)b * NN * CC;
    __nv_bfloat16* ohi = g_xhi + (size_t)b * NN * CC;
    __nv_bfloat16* olo = g_xlo + (size_t)b * NN * CC;
#pragma unroll
    for (int i = 0; i < 32; i += 8) {
        float v = tile[tx][ty + i];
        size_t idx = (size_t)(n0 + ty + i) * CC + c0 + tx;
        oxt[idx] = v;
        __nv_bfloat16 h = __float2bfloat16(v);
        ohi[idx] = h;
        olo[idx] = __float2bfloat16(v - __bfloat162float(h));
    }
}

// ---------------------------------------------------------------------------
// Kernel 2: W -> Whi/Wlo bf16
// ---------------------------------------------------------------------------
__global__ void wsplit_kernel(const float* __restrict__ W) {
    int t = blockIdx.x * 256 + threadIdx.x;
    if (t < COUT * TWOC) {
        float v = W[t];
        __nv_bfloat16 h = __float2bfloat16(v);
        g_whi[t] = h;
        g_wlo[t] = __float2bfloat16(v - __bfloat162float(h));
    }
}

// ---------------------------------------------------------------------------
// Kernel 3: gather + max-relative -> relhi/rello bf16 [B,N,C] (register-direct)
// ---------------------------------------------------------------------------
#define GA_NODES 32

__device__ __forceinline__ void split_st2(float2 v, __nv_bfloat16* ph, __nv_bfloat16* pl) {
    __nv_bfloat16 hx = __float2bfloat16(v.x), hy = __float2bfloat16(v.y);
    __nv_bfloat162 h; h.x = hx; h.y = hy;
    __nv_bfloat162 l;
    l.x = __float2bfloat16(v.x - __bfloat162float(hx));
    l.y = __float2bfloat16(v.y - __bfloat162float(hy));
    *(__nv_bfloat162*)ph = h;
    *(__nv_bfloat162*)pl = l;
}

__global__ __launch_bounds__(256) void gather_kernel(const int* __restrict__ edge) {
    __shared__ int sj[GA_NODES * KK];
    __shared__ int si[GA_NODES * KK];

    const int tid = threadIdx.x;
    const int bid = blockIdx.x;
    const int b   = bid >> 8;
    const int n0  = (bid & 255) * GA_NODES;

    const int* ej = edge + ((size_t)b * NN + n0) * KK;
    const int* ei = edge + ((size_t)(BB + b) * NN + n0) * KK;
    for (int t = tid; t < GA_NODES * KK; t += 256) {
        sj[t] = ej[t];
        si[t] = ei[t];
    }
    __syncthreads();

    const float* bx = g_xt + (size_t)b * NN * CC;
    __nv_bfloat16* rhb = g_rhi + (size_t)(b * NN + n0) * CC;
    __nv_bfloat16* rlb = g_rlo + (size_t)(b * NN + n0) * CC;
    const int wid  = tid >> 5;
    const int lane = tid & 31;
    const int cb   = lane * 2;

#pragma unroll
    for (int t = 0; t < 2; t++) {
        const int nA = wid + t * 16;
        const int nB = nA + 8;
        float2 a0 = make_float2(-3.0e38f, -3.0e38f), a1 = a0, a2 = a0;
        float2 b0v = a0, b1 = a0, b2 = a0;
        const int* sjA = sj + nA * KK; const int* siA = si + nA * KK;
        const int* sjB = sj + nB * KK; const int* siB = si + nB * KK;
#pragma unroll 2
        for (int k = 0; k < KK; k++) {
            const float* pjA = bx + (size_t)sjA[k] * CC + cb;
            const float* piA = bx + (size_t)siA[k] * CC + cb;
            const float* pjB = bx + (size_t)sjB[k] * CC + cb;
            const float* piB = bx + (size_t)siB[k] * CC + cb;
            float2 ja0 = *(const float2*)(pjA);       float2 ia0 = *(const float2*)(piA);
            float2 ja1 = *(const float2*)(pjA + 64);  float2 ia1 = *(const float2*)(piA + 64);
            float2 ja2 = *(const float2*)(pjA + 128); float2 ia2 = *(const float2*)(piA + 128);
            float2 jb0 = *(const float2*)(pjB);       float2 ib0 = *(const float2*)(piB);
            float2 jb1 = *(const float2*)(pjB + 64);  float2 ib1 = *(const float2*)(piB + 64);
            float2 jb2 = *(const float2*)(pjB + 128); float2 ib2 = *(const float2*)(piB + 128);
            a0.x = fmaxf(a0.x, ja0.x - ia0.x); a0.y = fmaxf(a0.y, ja0.y - ia0.y);
            a1.x = fmaxf(a1.x, ja1.x - ia1.x); a1.y = fmaxf(a1.y, ja1.y - ia1.y);
            a2.x = fmaxf(a2.x, ja2.x - ia2.x); a2.y = fmaxf(a2.y, ja2.y - ia2.y);
            b0v.x = fmaxf(b0v.x, jb0.x - ib0.x); b0v.y = fmaxf(b0v.y, jb0.y - ib0.y);
            b1.x = fmaxf(b1.x, jb1.x - ib1.x); b1.y = fmaxf(b1.y, jb1.y - ib1.y);
            b2.x = fmaxf(b2.x, jb2.x - ib2.x); b2.y = fmaxf(b2.y, jb2.y - ib2.y);
        }
        split_st2(a0,  rhb + (size_t)nA * CC + cb,       rlb + (size_t)nA * CC + cb);
        split_st2(a1,  rhb + (size_t)nA * CC + cb + 64,  rlb + (size_t)nA * CC + cb + 64);
        split_st2(a2,  rhb + (size_t)nA * CC + cb + 128, rlb + (size_t)nA * CC + cb + 128);
        split_st2(b0v, rhb + (size_t)nB * CC + cb,       rlb + (size_t)nB * CC + cb);
        split_st2(b1,  rhb + (size_t)nB * CC + cb + 64,  rlb + (size_t)nB * CC + cb + 64);
        split_st2(b2,  rhb + (size_t)nB * CC + cb + 128, rlb + (size_t)nB * CC + cb + 128);
    }
}

// ---------------------------------------------------------------------------
// Kernel 4: HMMA GEMM (mma.sync m16n8k16 bf16, 3-term split).
// Block: 256 thr (8 warps), tile = 64 nodes x 192 outs, K = 384 in 12 chunks.
// Warp (wm, wn): wm in {0,1} -> 32 nodes, wn in {0..3} -> 48 outs.
// ---------------------------------------------------------------------------
#define ASTR 40    // smem row stride in bf16 (80B: rows 0..7 hit distinct banks)

#define SA_H 0
#define SA_L (64 * ASTR)
#define SB_H (2 * 64 * ASTR)
#define SB_L (2 * 64 * ASTR + 192 * ASTR)
#define HM_SMEM ((2 * 64 * ASTR + 2 * 192 * ASTR) * 2)   // 40960 bytes

__device__ __forceinline__ void ldsm_x4(uint32_t a[4], uint32_t addr) {
    asm volatile("ldmatrix.sync.aligned.m8n8.x4.shared.b16 {%0,%1,%2,%3}, [%4];"
                 : "=r"(a[0]), "=r"(a[1]), "=r"(a[2]), "=r"(a[3]) : "r"(addr));
}
__device__ __forceinline__ void ldsm_x2(uint32_t a[2], uint32_t addr) {
    asm volatile("ldmatrix.sync.aligned.m8n8.x2.shared.b16 {%0,%1}, [%2];"
                 : "=r"(a[0]), "=r"(a[1]) : "r"(addr));
}
__device__ __forceinline__ void mma_bf16(float c[4], const uint32_t a[4],
                                         const uint32_t b[2]) {
    asm volatile(
        "mma.sync.aligned.m16n8k16.row.col.f32.bf16.bf16.f32 "
        "{%0,%1,%2,%3}, {%4,%5,%6,%7}, {%8,%9}, {%0,%1,%2,%3};"
        : "+f"(c[0]), "+f"(c[1]), "+f"(c[2]), "+f"(c[3])
        : "r"(a[0]), "r"(a[1]), "r"(a[2]), "r"(a[3]), "r"(b[0]), "r"(b[1]));
}

__global__ __launch_bounds__(256)
void gemm_hmma_kernel(const float* __restrict__ bias, float* __restrict__ out) {
    extern __shared__ char smem[];
    __nv_bfloat16* sm16 = (__nv_bfloat16*)smem;
    float* stg = (float*)smem;               // epilogue staging (aliases, post-loop)
    uint32_t sb = smem_u32(smem);

    const int tid  = threadIdx.x;
    const int lane = tid & 31;
    const int wid  = tid >> 5;
    const int wm   = wid & 1;                 // node half: 32 rows
    const int wn   = wid >> 1;                // out quarter: 48 cols
    const int b    = blockIdx.x >> 7;
    const int n0   = (blockIdx.x & 127) * 64;

    const __nv_bfloat16* xh = g_xhi + (size_t)(b * NN + n0) * CC;
    const __nv_bfloat16* xl = g_xlo + (size_t)(b * NN + n0) * CC;
    const __nv_bfloat16* rh = g_rhi + (size_t)(b * NN + n0) * CC;
    const __nv_bfloat16* rl = g_rlo + (size_t)(b * NN + n0) * CC;

    float acc[2][6][4];
#pragma unroll
    for (int mt = 0; mt < 2; mt++)
#pragma unroll
        for (int nt = 0; nt < 6; nt++)
#pragma unroll
            for (int e = 0; e < 4; e++) acc[mt][nt][e] = 0.0f;

    const int arow = tid >> 2, aseg = tid & 3;   // A staging: 64 rows x 4 segs

    for (int c = 0; c < 12; c++) {
        const int kc = c * 32;
        const __nv_bfloat16* Ah;
        const __nv_bfloat16* Al;
        int ac;
        if (kc < CC) { Ah = xh; Al = xl; ac = kc; }
        else         { Ah = rh; Al = rl; ac = kc - CC; }

        __syncthreads();   // previous iter's ldmatrix done before overwrite
        *(uint4*)(sm16 + SA_H + arow * ASTR + aseg * 8) =
            *(const uint4*)(Ah + (size_t)arow * CC + ac + aseg * 8);
        *(uint4*)(sm16 + SA_L + arow * ASTR + aseg * 8) =
            *(const uint4*)(Al + (size_t)arow * CC + ac + aseg * 8);
#pragma unroll
        for (int it = 0; it < 3; it++) {
            int idx = it * 256 + tid;
            int row = idx >> 2, seg = idx & 3;
            *(uint4*)(sm16 + SB_H + row * ASTR + seg * 8) =
                *(const uint4*)(g_whi + (size_t)row * TWOC + kc + seg * 8);
            *(uint4*)(sm16 + SB_L + row * ASTR + seg * 8) =
                *(const uint4*)(g_wlo + (size_t)row * TWOC + kc + seg * 8);
        }
        __syncthreads();

#pragma unroll
        for (int ks = 0; ks < 32; ks += 16) {
            // A fragments (m16k16): rows m0+lane%16, cols ks + (lane/16)*8
            uint32_t ah[2][4], al[2][4];
#pragma unroll
            for (int mt = 0; mt < 2; mt++) {
                int m0 = wm * 32 + mt * 16;
                uint32_t off =
                    ((m0 + (lane & 15)) * ASTR + ks + ((lane >> 4) << 3)) * 2;
                ldsm_x4(ah[mt], sb + SA_H * 2 + off);
                ldsm_x4(al[mt], sb + SA_L * 2 + off);
            }
            // B fragments (n8k16): rows o0+lane%8, cols ks + ((lane/8)&1)*8
            uint32_t bh[6][2], bl[6][2];
#pragma unroll
            for (int nt = 0; nt < 6; nt++) {
                int o0 = wn * 48 + nt * 8;
                uint32_t off =
                    ((o0 + (lane & 7)) * ASTR + ks + (((lane >> 3) & 1) << 3)) * 2;
                ldsm_x2(bh[nt], sb + SB_H * 2 + off);
                ldsm_x2(bl[nt], sb + SB_L * 2 + off);
            }
#pragma unroll
            for (int mt = 0; mt < 2; mt++)
#pragma unroll
                for (int nt = 0; nt < 6; nt++) {
                    mma_bf16(acc[mt][nt], ah[mt], bh[nt]);
                    mma_bf16(acc[mt][nt], ah[mt], bl[nt]);
                    mma_bf16(acc[mt][nt], al[mt], bh[nt]);
                }
        }
    }

    // Epilogue: per out-quarter, restage [48 outs][64 nodes] in smem, then
    // coalesced stores with bias+relu. out layout [b][o][n].
    const int g   = lane >> 2;    // row group in D frag
    const int tig = lane & 3;     // col pair in D frag
    for (int q = 0; q < 4; q++) {
        __syncthreads();
        if (wn == q) {
#pragma unroll
            for (int mt = 0; mt < 2; mt++)
#pragma unroll
                for (int nt = 0; nt < 6; nt++)
#pragma unroll
                    for (int e = 0; e < 4; e++) {
                        int m  = wm * 32 + mt * 16 + g + ((e >> 1) << 3);
                        int ol = nt * 8 + tig * 2 + (e & 1);
                        stg[ol * 65 + m] = acc[mt][nt][e];
                    }
        }
        __syncthreads();
#pragma unroll
        for (int it = 0; it < 12; it++) {
            int idx = it * 256 + tid;
            int r = idx >> 6, cn = idx & 63;
            int o = q * 48 + r;
            float v = stg[r * 65 + cn] + bias[o];
            out[((size_t)b * COUT + o) * NN + n0 + cn] = fmaxf(v, 0.0f);
        }
    }
}

// ---------------------------------------------------------------------------
// Launch (sequential, default stream)
// ---------------------------------------------------------------------------
extern "C" void kernel_launch(void* const* d_in, const int* in_sizes, int n_in,
                              void* d_out, int out_size) {
    const float* x    = (const float*)d_in[0];
    const int*   edge = (const int*)d_in[2];
    const float* W    = (const float*)d_in[3];
    const float* bias = (const float*)d_in[4];
    float*       out  = (float*)d_out;

    wsplit_kernel<<<(COUT * TWOC + 255) / 256, 256>>>(W);
    transpose_kernel<<<dim3(NN / 32, CC / 32, BB), dim3(32, 8)>>>(x);
    gather_kernel<<<BB * (NN / GA_NODES), 256>>>(edge);
    gemm_hmma_kernel<<<BB * (NN / 64), 256, HM_SMEM>>>(bias, out);
}